// round 12
// baseline (speedup 1.0000x reference)
#include <cuda_runtime.h>
#include <cstdint>

#define BATCH   32
#define NPRED   8400
#define NCLS    80
#define ROWF    85
#define KPRE    512
#define MAXOUT  100
#define RPB     24          // rows per k_score block: 24*85*4 = 8160 B = 510 float4
#define CONF_TH 0.25f
#define IOU_TH  0.45f
#define CLS_OFF 4096.0f
#define FULLM   0xFFFFFFFFu

// Scratch (no allocations allowed -> device globals)
__device__ unsigned long long g_keys[BATCH * NPRED];
__device__ unsigned long long g_topk[BATCH * KPRE];
__device__ float              g_rows[(size_t)BATCH * NPRED * 8]; // x1,y1,x2,y2,obj,conf,cls,pad

// ---------------------------------------------------------------------------
// K1: streaming pass. Block stages 24 rows (510 aligned float4) into smem
// with fully-coalesced LDG.128; warp-per-row argmax reduce; emits both the
// sort key (score_bits<<32 | ~n, unique) and the full 8-float det record.
// ---------------------------------------------------------------------------
__global__ void k_score(const float* __restrict__ pred) {
    __shared__ float srow[RPB * ROWF];     // 8160 B
    int tid = threadIdx.x;                 // 384
    int warp = tid >> 5, lane = tid & 31;  // 12 warps
    int b = blockIdx.y;
    int row0 = blockIdx.x * RPB;

    const float4* src = (const float4*)(pred + ((size_t)b * NPRED + row0) * ROWF);
    float4* dst4 = (float4*)srow;
    for (int i = tid; i < RPB * ROWF / 4; i += 384) dst4[i] = src[i];
    __syncthreads();

#pragma unroll
    for (int rr = 0; rr < 2; rr++) {
        int r = warp * 2 + rr;             // 0..23
        const float* row = srow + r * ROWF;
        float bv = -1.f; int bi = 0;
#pragma unroll
        for (int i = 0; i < 3; i++) {
            int c = lane + i * 32;
            if (c < NCLS) {
                float v = row[5 + c];
                if (v > bv) { bv = v; bi = c; }
            }
        }
#pragma unroll
        for (int off = 16; off; off >>= 1) {
            float ov = __shfl_xor_sync(FULLM, bv, off);
            int   oi = __shfl_xor_sync(FULLM, bi, off);
            if (ov > bv || (ov == bv && oi < bi)) { bv = ov; bi = oi; }
        }
        if (lane == 0) {
            float cx = row[0], cy = row[1], w = row[2], h = row[3], obj = row[4];
            float score = obj * bv;                   // >= 0
            unsigned sb = __float_as_uint(score);     // positive-float bit order == int order
            int n = row0 + r;
            g_keys[(size_t)b * NPRED + n] =
                ((unsigned long long)sb << 32) | (unsigned)(~(unsigned)n);
            float x1 = cx - 0.5f * w, y1 = cy - 0.5f * h;
            float x2 = cx + 0.5f * w, y2 = cy + 0.5f * h;
            float4* rec = (float4*)(g_rows + ((size_t)b * NPRED + n) * 8);
            rec[0] = make_float4(x1, y1, x2, y2);
            rec[1] = make_float4(obj, bv, (float)bi, 0.f);
        }
    }
}

// ---------------------------------------------------------------------------
// K2: per-batch conf (= min(0.25, max score)) + exact top-512 select +
// bitonic sort descending. Radix over the 4 score bytes, then direct pick
// among candidates sharing the 32-bit score prefix (<=256 a.s.; full radix
// fallback otherwise). One 512-thread block per batch.
// ---------------------------------------------------------------------------
__global__ void k_select() {
    extern __shared__ unsigned long long s_keys[];   // NPRED + KPRE entries
    unsigned long long* topsm = s_keys + NPRED;

    __shared__ unsigned int        hist[256];
    __shared__ unsigned int        wmax[16];
    __shared__ unsigned int        sh_confb;
    __shared__ unsigned long long  sh_prefix;
    __shared__ unsigned long long  sh_pivot;
    __shared__ int                 sh_remaining;
    __shared__ unsigned int        cnt;
    __shared__ unsigned long long  cand[256];
    __shared__ unsigned int        ccnt;

    int b = blockIdx.x;
    int tid = threadIdx.x;                 // 512
    int warp = tid >> 5, lane = tid & 31;  // 16 warps
    const int NITER = (NPRED + 511) / 512; // uniform trip count (17)

    // load keys + running max of score field
    unsigned mymax = 0u;
    for (int i = tid; i < NPRED; i += 512) {
        unsigned long long k = g_keys[(size_t)b * NPRED + i];
        s_keys[i] = k;
        unsigned sb = (unsigned)(k >> 32);
        mymax = mymax > sb ? mymax : sb;
    }
#pragma unroll
    for (int off = 16; off; off >>= 1) {
        unsigned v = __shfl_xor_sync(FULLM, mymax, off);
        mymax = mymax > v ? mymax : v;
    }
    if (lane == 0) wmax[warp] = mymax;
    __syncthreads();
    if (tid < 32) {
        unsigned v = (lane < 16) ? wmax[lane] : 0u;
#pragma unroll
        for (int off = 16; off; off >>= 1) {
            unsigned o = __shfl_xor_sync(FULLM, v, off);
            v = v > o ? v : o;
        }
        if (lane == 0) {
            float conf = fminf(CONF_TH, __uint_as_float(v));
            sh_confb = __float_as_uint(conf);
            sh_prefix = 0ull;
            sh_remaining = KPRE;
            ccnt = 0u;
        }
    }
    __syncthreads();
    unsigned confb = sh_confb;

    // mask invalid (score < conf) -> score field 0 (acts as -inf; index kept)
    for (int i = tid; i < NPRED; i += 512) {
        unsigned long long k = s_keys[i];
        if ((unsigned)(k >> 32) < confb) s_keys[i] = k & 0xFFFFFFFFull;
    }
    __syncthreads();

    // 4x 8-bit radix passes over the score bytes (7..4)
    for (int p = 7; p >= 4; p--) {
        if (tid < 256) hist[tid] = 0u;
        __syncthreads();
        unsigned long long pref = sh_prefix;
        for (int it = 0; it < NITER; it++) {
            int i = it * 512 + tid;
            unsigned bucket = 0x100u;      // sentinel: inactive / non-matching
            if (i < NPRED) {
                unsigned long long k = s_keys[i];
                bool match = (p == 7) || ((k >> ((p + 1) * 8)) == pref);
                if (match) bucket = (unsigned)(k >> (p * 8)) & 0xFFu;
            }
            unsigned peers = __match_any_sync(FULLM, bucket);
            if (bucket != 0x100u && ((__ffs(peers) - 1) == lane))
                atomicAdd(&hist[bucket], __popc(peers));
        }
        __syncthreads();
        if (tid < 32) {
            int rem = sh_remaining;
            unsigned s = 0;
#pragma unroll
            for (int q = 0; q < 8; q++) s += hist[(lane << 3) + q];
            unsigned S = s;                // inclusive suffix sum across lanes
#pragma unroll
            for (int off = 1; off < 32; off <<= 1) {
                unsigned v = __shfl_down_sync(FULLM, S, off);
                if (lane + off < 32) S += v;
            }
            unsigned bal = __ballot_sync(FULLM, (int)S >= rem);
            int L = 31 - __clz(bal);       // highest lane group reaching rem
            if (lane == L) {
                int cum = (int)(S - s);    // suffix excluding this group
                for (int bb = (L << 3) + 7; bb >= (L << 3); bb--) {
                    cum += (int)hist[bb];
                    if (cum >= rem) {
                        sh_remaining = rem - (cum - (int)hist[bb]);
                        sh_prefix = (pref << 8) | (unsigned)bb;
                        break;
                    }
                }
            }
        }
        __syncthreads();
    }

    // collect keys whose score field equals the 32-bit prefix
    unsigned prefix32 = (unsigned)sh_prefix;
    for (int i = tid; i < NPRED; i += 512) {
        unsigned long long k = s_keys[i];
        if ((unsigned)(k >> 32) == prefix32) {
            unsigned pos = atomicAdd(&ccnt, 1u);
            if (pos < 256) cand[pos] = k;
        }
    }
    __syncthreads();

    if (ccnt <= 256u) {
        // direct pick: rem-th largest among candidates (keys unique)
        int rem = sh_remaining;
        if (tid < (int)ccnt) {
            unsigned long long k = cand[tid];
            int g = 0;
            for (unsigned j = 0; j < ccnt; j++) g += (cand[j] > k);
            if (g == rem - 1) sh_pivot = k;
        }
        __syncthreads();
    } else {
        // fallback: finish the remaining 4 radix passes (index bytes)
        for (int p = 3; p >= 0; p--) {
            if (tid < 256) hist[tid] = 0u;
            __syncthreads();
            unsigned long long pref = sh_prefix;
            for (int it = 0; it < NITER; it++) {
                int i = it * 512 + tid;
                unsigned bucket = 0x100u;
                if (i < NPRED) {
                    unsigned long long k = s_keys[i];
                    bool match = ((k >> ((p + 1) * 8)) == pref);
                    if (match) bucket = (unsigned)(k >> (p * 8)) & 0xFFu;
                }
                unsigned peers = __match_any_sync(FULLM, bucket);
                if (bucket != 0x100u && ((__ffs(peers) - 1) == lane))
                    atomicAdd(&hist[bucket], __popc(peers));
            }
            __syncthreads();
            if (tid < 32) {
                int rem = sh_remaining;
                unsigned s = 0;
#pragma unroll
                for (int q = 0; q < 8; q++) s += hist[(lane << 3) + q];
                unsigned S = s;
#pragma unroll
                for (int off = 1; off < 32; off <<= 1) {
                    unsigned v = __shfl_down_sync(FULLM, S, off);
                    if (lane + off < 32) S += v;
                }
                unsigned bal = __ballot_sync(FULLM, (int)S >= rem);
                int L = 31 - __clz(bal);
                if (lane == L) {
                    int cum = (int)(S - s);
                    for (int bb = (L << 3) + 7; bb >= (L << 3); bb--) {
                        cum += (int)hist[bb];
                        if (cum >= rem) {
                            sh_remaining = rem - (cum - (int)hist[bb]);
                            sh_prefix = (pref << 8) | (unsigned)bb;
                            break;
                        }
                    }
                }
            }
            __syncthreads();
        }
        if (tid == 0) sh_pivot = sh_prefix;
        __syncthreads();
    }

    unsigned long long pivot = sh_pivot;   // exact 512th-largest key
    if (tid == 0) cnt = 0u;
    __syncthreads();

    // compact: keys unique -> exactly KPRE keys >= pivot
    for (int i = tid; i < NPRED; i += 512) {
        unsigned long long k = s_keys[i];
        if (k >= pivot) {
            unsigned pos = atomicAdd(&cnt, 1u);
            topsm[pos] = k;
        }
    }
    __syncthreads();

    // bitonic sort descending (512 elems, 512 threads)
    for (int kk = 2; kk <= KPRE; kk <<= 1) {
        for (int j = kk >> 1; j > 0; j >>= 1) {
            int ixj = tid ^ j;
            if (ixj > tid) {
                bool up = ((tid & kk) == 0);
                unsigned long long a = topsm[tid], c = topsm[ixj];
                bool sw = up ? (a < c) : (a > c);
                if (sw) { topsm[tid] = c; topsm[ixj] = a; }
            }
            __syncthreads();
        }
    }

    for (int i = tid; i < KPRE; i += 512)
        g_topk[(size_t)b * KPRE + i] = topsm[i];
}

// ---------------------------------------------------------------------------
// K3: fused gather + on-demand IoU + greedy NMS + emit. One 512-thread block
// per batch. IoU computed only for kept boxes' rows (~100 of 512): when box i
// is kept, all 512 threads compute iou(i, tid) in parallel; per-warp ballots
// clear the alive mask. Early exit at 100 kept.
// ---------------------------------------------------------------------------
__global__ void k_nms(float* __restrict__ out, int out_size) {
    __shared__ float sx1[KPRE], sy1[KPRE], sx2[KPRE], sy2[KPRE], sar[KPRE];
    __shared__ int   sn[KPRE];
    __shared__ unsigned salive[16];
    __shared__ int   skept[MAXOUT];
    __shared__ int   s_i;

    int b = blockIdx.x, tid = threadIdx.x;   // 512
    int warp = tid >> 5, lane = tid & 31;

    // gather: extract source row from key, load 8-float record, build offset box
    {
        unsigned long long key = g_topk[(size_t)b * KPRE + tid];
        unsigned sb = (unsigned)(key >> 32);
        int n = (int)(~(unsigned)key);
        sn[tid] = n;
        const float4* rec = (const float4*)(g_rows + ((size_t)b * NPRED + n) * 8);
        float4 r0 = rec[0];                  // x1,y1,x2,y2
        float4 r1 = rec[1];                  // obj,conf,cls,pad
        float off = r1.z * CLS_OFF;
        sx1[tid] = r0.x + off; sy1[tid] = r0.y + off;
        sx2[tid] = r0.z + off; sy2[tid] = r0.w + off;
        sar[tid] = (r0.z - r0.x) * (r0.w - r0.y);
        unsigned w = __ballot_sync(FULLM, sb != 0u);
        if (lane == 0) salive[warp] = w;
    }
    __syncthreads();

    // greedy NMS: find first alive, suppress its overlaps, repeat
    int nk = 0;
    while (nk < MAXOUT) {
        if (tid < 32) {
            unsigned a = (tid < 16) ? salive[tid] : 0u;
            unsigned bal = __ballot_sync(FULLM, a != 0u);
            int tl = bal ? (__ffs(bal) - 1) : 0;
            unsigned w = __shfl_sync(FULLM, a, tl);
            int bit = __ffs(w) - 1;
            if (tid == 0) s_i = bal ? ((tl << 5) + bit) : -1;
        }
        __syncthreads();
        int i = s_i;
        if (i < 0) break;                    // uniform
        if (tid == 0) skept[nk] = i;

        // all threads: iou(box i, box tid)
        float ix1 = fmaxf(sx1[i], sx1[tid]);
        float iy1 = fmaxf(sy1[i], sy1[tid]);
        float ix2 = fminf(sx2[i], sx2[tid]);
        float iy2 = fminf(sy2[i], sy2[tid]);
        float iw = fmaxf(ix2 - ix1, 0.f);
        float ih = fmaxf(iy2 - iy1, 0.f);
        float inter = iw * ih;
        float uni = sar[i] + sar[tid] - inter;
        float iou = inter / (uni + 1e-9f);
        unsigned bits = __ballot_sync(FULLM, iou > IOU_TH);
        if (lane == 0) {
            unsigned clr = bits | ((warp == (i >> 5)) ? (1u << (i & 31)) : 0u);
            salive[warp] &= ~clr;            // suppress overlaps + self
        }
        __syncthreads();
        nk++;
    }

    // emit: kept entries ascending -> rows [0, nk); remaining rows zeroed
    float* dets = out + (size_t)b * MAXOUT * 7;
    bool has_mask = (out_size >= BATCH * MAXOUT * 7 + BATCH * MAXOUT);
    float* mask = out + (size_t)BATCH * MAXOUT * 7 + (size_t)b * MAXOUT;

    if (tid < MAXOUT) {
        int r = tid;
        if (r < nk) {
            int i = skept[r];
            int n = sn[i];
            const float4* rec = (const float4*)(g_rows + ((size_t)b * NPRED + n) * 8);
            float4 r0 = rec[0];
            float4 r1 = rec[1];
            float* o = dets + (size_t)r * 7;
            o[0] = r0.x; o[1] = r0.y; o[2] = r0.z; o[3] = r0.w;
            o[4] = r1.x; o[5] = r1.y; o[6] = r1.z;
            if (has_mask) mask[r] = 1.0f;
        } else {
            float* o = dets + (size_t)r * 7;
#pragma unroll
            for (int c = 0; c < 7; c++) o[c] = 0.f;
            if (has_mask) mask[r] = 0.f;
        }
    }
}

// ---------------------------------------------------------------------------
extern "C" void kernel_launch(void* const* d_in, const int* in_sizes, int n_in,
                              void* d_out, int out_size) {
    (void)in_sizes; (void)n_in;
    const float* pred = (const float*)d_in[0];
    float* out = (float*)d_out;

    static_assert(NPRED % RPB == 0, "rows per block");
    static_assert((RPB * ROWF) % 4 == 0, "float4 staging");
    static_assert((NPRED * ROWF) % 4 == 0, "float4 batch base");

    cudaFuncSetAttribute(k_select, cudaFuncAttributeMaxDynamicSharedMemorySize,
                         (NPRED + KPRE) * 8);

    dim3 gs(NPRED / RPB, BATCH);           // (350, 32)
    k_score<<<gs, 384>>>(pred);
    k_select<<<BATCH, 512, (NPRED + KPRE) * 8>>>();
    k_nms<<<BATCH, 512>>>(out, out_size);
}